// round 3
// baseline (speedup 1.0000x reference)
#include <cuda_runtime.h>
#include <cuda_bf16.h>

// Shapes
#define Bn 8
#define Ln 128
#define Hn 768
#define Rn 24
#define Mn (Bn*Ln)   // 1024

// ---------------- scratch (__device__ globals; no allocation) ----------------
__device__ float g_pool[Bn*Hn];            // 8x768
__device__ float g_bias[2*Bn*Hn];          // [sh|oh][b][n]
__device__ float g_At[Bn*Hn*Ln];           // A transposed: [b][h][j]
__device__ float g_Ct[Bn*Hn*Ln];           // C' transposed (b_corr folded): [b][h][i]
__device__ float g_Sh[Mn*Hn];              // relu subj hidden
__device__ float g_Oh[Mn*Hn];              // relu obj hidden

// ---------------- f32x2 helpers (sm_103a packed FMA) ----------------
__device__ __forceinline__ unsigned long long pk2(float x, float y) {
    unsigned long long r;
    asm("mov.b64 %0,{%1,%2};" : "=l"(r) : "f"(x), "f"(y));
    return r;
}
__device__ __forceinline__ unsigned long long fma2(unsigned long long a,
                                                   unsigned long long b,
                                                   unsigned long long c) {
    unsigned long long d;
    asm("fma.rn.f32x2 %0,%1,%2,%3;" : "=l"(d) : "l"(a), "l"(b), "l"(c));
    return d;
}
__device__ __forceinline__ void upk2(unsigned long long v, float& x, float& y) {
    asm("mov.b64 {%0,%1},%2;" : "=f"(x), "=f"(y) : "l"(v));
}

// ---------------- 1) masked mean pool ----------------
__global__ __launch_bounds__(256) void pool_kernel(const float* __restrict__ e,
                                                   const float* __restrict__ mask) {
    int b = blockIdx.x;
    int h = blockIdx.y * 256 + threadIdx.x;   // grid.y = 3
    __shared__ float msm[Ln];
    __shared__ float sinv;
    int tid = threadIdx.x;
    if (tid < Ln) msm[tid] = mask[b*Ln + tid];
    __syncthreads();
    if (tid == 0) {
        float s = 0.f;
        for (int l = 0; l < Ln; l++) s += msm[l];
        sinv = 1.f / s;
    }
    __syncthreads();
    const float* ep = e + (size_t)b*Ln*Hn + h;
    float acc = 0.f;
    #pragma unroll 8
    for (int l = 0; l < Ln; l++) acc += ep[(size_t)l*Hn] * msm[l];
    g_pool[b*Hn + h] = acc * sinv;
}

// ---------------- 2) stage1: relu(pool@W_hr+b)@W_rj+b ----------------
__global__ __launch_bounds__(384) void stage1_kernel(const float* __restrict__ W_hr,
                                                     const float* __restrict__ b_hr,
                                                     const float* __restrict__ W_rj,
                                                     const float* __restrict__ b_rj,
                                                     float* __restrict__ out) {
    int b = blockIdx.x;
    int tid = threadIdx.x;   // 384
    __shared__ float ps[Hn];
    __shared__ float rh[Hn/2];
    for (int h = tid; h < Hn; h += 384) ps[h] = g_pool[b*Hn + h];
    __syncthreads();
    float acc = b_hr[tid];
    #pragma unroll 8
    for (int h = 0; h < Hn; h++) acc += ps[h] * W_hr[h*(Hn/2) + tid];
    rh[tid] = fmaxf(acc, 0.f);
    __syncthreads();
    if (tid < Rn) {
        float a2 = b_rj[tid];
        #pragma unroll 8
        for (int r = 0; r < Hn/2; r++) a2 += rh[r] * W_rj[r*Rn + tid];
        out[b*Rn + tid] = a2;
    }
}

// ---------------- 3) per-batch fusion biases: re@W_top + b ----------------
__global__ __launch_bounds__(256) void bias_kernel(const float* __restrict__ rel_emb,
                                                   const int* __restrict__ target,
                                                   const float* __restrict__ W_sh,
                                                   const float* __restrict__ b_sh,
                                                   const float* __restrict__ W_oh,
                                                   const float* __restrict__ b_oh) {
    int n = blockIdx.x * 256 + threadIdx.x;   // grid.x = 3
    int b = blockIdx.y;
    int z = blockIdx.z;                        // 0=sh, 1=oh
    const float* W = z ? W_oh : W_sh;          // top half rows 0..767
    const float* bias = z ? b_oh : b_sh;
    const float* re = rel_emb + (size_t)target[b]*Hn;
    float acc = 0.f;
    #pragma unroll 8
    for (int h = 0; h < Hn; h++) acc += re[h] * W[(size_t)h*Hn + n];
    g_bias[z*Bn*Hn + b*Hn + n] = acc + bias[n];
}

// ---------------- 4) unified GEMM: embed(1024x768) @ W(768x768) ----------------
// z=0: A  -> g_At transposed, no bias
// z=1: C  -> g_Ct transposed, + b_corr
// z=2: Sh -> relu(. + g_bias[0][b]) normal layout
// z=3: Oh -> relu(. + g_bias[1][b]) normal layout
#define BM 64
#define BN 64
#define BK 16
__global__ __launch_bounds__(256) void gemm_kernel(const float* __restrict__ X,
                                                   const float* __restrict__ W_corr,
                                                   const float* __restrict__ W_sh,
                                                   const float* __restrict__ W_oh,
                                                   const float* __restrict__ b_corr) {
    int z = blockIdx.z;
    const float* W;
    if (z == 0)      W = W_corr;
    else if (z == 1) W = W_corr + Hn*Hn;
    else if (z == 2) W = W_sh  + Hn*Hn;
    else             W = W_oh  + Hn*Hn;

    int m0 = blockIdx.y * BM;
    int n0 = blockIdx.x * BN;
    int tid = threadIdx.x;

    __shared__ float As[2][BK][BM];
    __shared__ float Bs[2][BK][BN];

    int arow = tid >> 2;            // 0..63
    int acol = (tid & 3) * 4;       // 0..12
    int brow = tid >> 4;            // 0..15
    int bcol = (tid & 15) * 4;      // 0..60

    const float* Aptr = X + (size_t)(m0 + arow)*Hn + acol;
    const float* Bptr = W + (size_t)brow*Hn + n0 + bcol;

    float4 av = *(const float4*)Aptr;
    float4 bv = *(const float4*)Bptr;
    As[0][acol+0][arow] = av.x;
    As[0][acol+1][arow] = av.y;
    As[0][acol+2][arow] = av.z;
    As[0][acol+3][arow] = av.w;
    *(float4*)&Bs[0][brow][bcol] = bv;
    __syncthreads();

    int tx = tid & 15, ty = tid >> 4;
    unsigned long long acc2[2][4];
    #pragma unroll
    for (int i = 0; i < 2; i++)
        #pragma unroll
        for (int j = 0; j < 4; j++) acc2[i][j] = 0ull;

    const int NT = Hn / BK;   // 48
    float4 aNxt, bNxt;
    for (int t = 0; t < NT; ++t) {
        int cur = t & 1;
        if (t + 1 < NT) {
            aNxt = *(const float4*)(Aptr + (t+1)*BK);
            bNxt = *(const float4*)(Bptr + (size_t)(t+1)*BK*Hn);
        }
        #pragma unroll
        for (int k = 0; k < BK; k++) {
            float4 af = *(const float4*)&As[cur][k][ty*4];
            float4 bf = *(const float4*)&Bs[cur][k][tx*4];
            unsigned long long a01 = pk2(af.x, af.y);
            unsigned long long a23 = pk2(af.z, af.w);
            unsigned long long bj;
            bj = pk2(bf.x, bf.x);
            acc2[0][0] = fma2(a01, bj, acc2[0][0]);
            acc2[1][0] = fma2(a23, bj, acc2[1][0]);
            bj = pk2(bf.y, bf.y);
            acc2[0][1] = fma2(a01, bj, acc2[0][1]);
            acc2[1][1] = fma2(a23, bj, acc2[1][1]);
            bj = pk2(bf.z, bf.z);
            acc2[0][2] = fma2(a01, bj, acc2[0][2]);
            acc2[1][2] = fma2(a23, bj, acc2[1][2]);
            bj = pk2(bf.w, bf.w);
            acc2[0][3] = fma2(a01, bj, acc2[0][3]);
            acc2[1][3] = fma2(a23, bj, acc2[1][3]);
        }
        if (t + 1 < NT) {
            int nxt = cur ^ 1;
            As[nxt][acol+0][arow] = aNxt.x;
            As[nxt][acol+1][arow] = aNxt.y;
            As[nxt][acol+2][arow] = aNxt.z;
            As[nxt][acol+3][arow] = aNxt.w;
            *(float4*)&Bs[nxt][brow][bcol] = bNxt;
        }
        __syncthreads();
    }

    float c[4][4];
    #pragma unroll
    for (int j = 0; j < 4; j++) {
        upk2(acc2[0][j], c[0][j], c[1][j]);
        upk2(acc2[1][j], c[2][j], c[3][j]);
    }

    if (z <= 1) {
        // transposed store: dst[b][n][l], fold b_corr for z==1
        int bb = m0 >> 7;               // batch (BM=64 never straddles batch)
        int lbase = (m0 & 127) + ty*4;  // local l, 4-aligned
        float* base = (z == 1) ? g_Ct : g_At;
        #pragma unroll
        for (int j = 0; j < 4; j++) {
            int n = n0 + tx*4 + j;
            float bias = (z == 1) ? __ldg(&b_corr[n]) : 0.f;
            float4 v = make_float4(c[0][j]+bias, c[1][j]+bias, c[2][j]+bias, c[3][j]+bias);
            *(float4*)&base[((size_t)bb*Hn + n)*Ln + lbase] = v;
        }
    } else {
        float* outp = (z == 2) ? g_Sh : g_Oh;
        const float* brow2 = g_bias + (z-2)*Bn*Hn + (m0 >> 7)*Hn + n0 + tx*4;
        float4 bias4 = *(const float4*)brow2;
        #pragma unroll
        for (int i = 0; i < 4; i++) {
            int m = m0 + ty*4 + i;
            float4 v = make_float4(fmaxf(c[i][0] + bias4.x, 0.f),
                                   fmaxf(c[i][1] + bias4.y, 0.f),
                                   fmaxf(c[i][2] + bias4.z, 0.f),
                                   fmaxf(c[i][3] + bias4.w, 0.f));
            *(float4*)&outp[(size_t)m*Hn + n0 + tx*4] = v;
        }
    }
}

// ---------------- 5) fused pred_corres ----------------
// out[b,i,j] = sum_h relu(A_t[b][h][j] + C_t[b][h][i]) * W_gc[h] + b_gc
#define CH 96
__global__ __launch_bounds__(256) void corres_kernel(const float* __restrict__ W_gc,
                                                     const float* __restrict__ b_gc,
                                                     float* __restrict__ outp) {
    int jt = blockIdx.x, it = blockIdx.y, b = blockIdx.z;
    __shared__ float Asm[CH][32];
    __shared__ float Csm[CH][32];
    __shared__ float Wsm[CH];
    int tid = threadIdx.x;
    int tx = tid & 15, ty = tid >> 4;

    const float* Abase = g_At + (size_t)b*Hn*Ln + jt*32;
    const float* Cbase = g_Ct + (size_t)b*Hn*Ln + it*32;

    float acc00 = 0.f, acc01 = 0.f, acc10 = 0.f, acc11 = 0.f;

    for (int hc = 0; hc < Hn; hc += CH) {
        __syncthreads();
        #pragma unroll
        for (int r = 0; r < 3; r++) {
            int idx = tid + r*256;           // 0..767 float4 slots
            int row = idx >> 3;
            int c4  = (idx & 7) << 2;
            *(float4*)&Asm[row][c4] = *(const float4*)&Abase[(size_t)(hc+row)*Ln + c4];
            *(float4*)&Csm[row][c4] = *(const float4*)&Cbase[(size_t)(hc+row)*Ln + c4];
        }
        if (tid < CH) Wsm[tid] = W_gc[hc + tid];
        __syncthreads();
        #pragma unroll 8
        for (int k = 0; k < CH; k++) {
            float2 a = *(const float2*)&Asm[k][tx*2];
            float2 c = *(const float2*)&Csm[k][ty*2];
            float w = Wsm[k];
            acc00 += fmaxf(a.x + c.x, 0.f) * w;
            acc01 += fmaxf(a.y + c.x, 0.f) * w;
            acc10 += fmaxf(a.x + c.y, 0.f) * w;
            acc11 += fmaxf(a.y + c.y, 0.f) * w;
        }
    }
    float bg = __ldg(b_gc);
    int i0 = it*32 + ty*2, j0 = jt*32 + tx*2;
    float* o = outp + ((size_t)b*Ln + i0)*Ln + j0;
    *(float2*)&o[0]   = make_float2(acc00 + bg, acc01 + bg);
    *(float2*)&o[Ln]  = make_float2(acc10 + bg, acc11 + bg);
}

// ---------------- 6) head projections: hidden(1024x768) @ (768x3) ----------------
__global__ __launch_bounds__(256) void head_kernel(const float* __restrict__ W_st,
                                                   const float* __restrict__ b_st,
                                                   const float* __restrict__ W_ot,
                                                   const float* __restrict__ b_ot,
                                                   float* __restrict__ out) {
    int z = blockIdx.y;  // 0=subj,1=obj
    const float* Hbuf = z ? g_Oh : g_Sh;
    const float* Wp = z ? W_ot : W_st;
    const float* bp = z ? b_ot : b_st;
    int w = threadIdx.x >> 5, lane = threadIdx.x & 31;
    int m = blockIdx.x * 8 + w;   // 0..1023
    float a0 = 0.f, a1 = 0.f, a2 = 0.f;
    const float* hr = Hbuf + (size_t)m*Hn;
    for (int h = lane; h < Hn; h += 32) {
        float v = hr[h];
        a0 += v * __ldg(&Wp[h*3 + 0]);
        a1 += v * __ldg(&Wp[h*3 + 1]);
        a2 += v * __ldg(&Wp[h*3 + 2]);
    }
    #pragma unroll
    for (int off = 16; off; off >>= 1) {
        a0 += __shfl_xor_sync(0xFFFFFFFFu, a0, off);
        a1 += __shfl_xor_sync(0xFFFFFFFFu, a1, off);
        a2 += __shfl_xor_sync(0xFFFFFFFFu, a2, off);
    }
    if (lane == 0) {
        float* o = out + (z ? (Rn*Bn + 3*Mn) : (Rn*Bn)) + m*3;
        o[0] = a0 + bp[0];
        o[1] = a1 + bp[1];
        o[2] = a2 + bp[2];
    }
}

// ---------------- launch ----------------
extern "C" void kernel_launch(void* const* d_in, const int* in_sizes, int n_in,
                              void* d_out, int out_size) {
    const float* embed   = (const float*)d_in[0];
    const float* mask    = (const float*)d_in[1];
    const int*   target  = (const int*)  d_in[2];
    const float* W_hr    = (const float*)d_in[3];
    const float* b_hr    = (const float*)d_in[4];
    const float* W_rj    = (const float*)d_in[5];
    const float* b_rj    = (const float*)d_in[6];
    const float* rel_emb = (const float*)d_in[7];
    const float* W_corr  = (const float*)d_in[8];
    const float* b_corr  = (const float*)d_in[9];
    const float* W_gc    = (const float*)d_in[10];
    const float* b_gc    = (const float*)d_in[11];
    const float* W_sh    = (const float*)d_in[12];
    const float* b_sh    = (const float*)d_in[13];
    const float* W_st    = (const float*)d_in[14];
    const float* b_st    = (const float*)d_in[15];
    const float* W_oh    = (const float*)d_in[16];
    const float* b_oh    = (const float*)d_in[17];
    const float* W_ot    = (const float*)d_in[18];
    const float* b_ot    = (const float*)d_in[19];
    float* out = (float*)d_out;

    // out layout: stage1[192] | subj[3072] | obj[3072] | pred_corres[131072]
    pool_kernel  <<<dim3(Bn, 3), 256>>>(embed, mask);
    stage1_kernel<<<Bn, 384>>>(W_hr, b_hr, W_rj, b_rj, out);
    bias_kernel  <<<dim3(3, Bn, 2), 256>>>(rel_emb, target, W_sh, b_sh, W_oh, b_oh);
    gemm_kernel  <<<dim3(Hn/BN, Mn/BM, 4), 256>>>(embed, W_corr, W_sh, W_oh, b_corr);
    corres_kernel<<<dim3(4, 4, Bn), 256>>>(W_gc, b_gc, out + Rn*Bn + 6*Mn);
    head_kernel  <<<dim3(Mn/8, 2), 256>>>(W_st, b_st, W_ot, b_ot, out);
}